// round 10
// baseline (speedup 1.0000x reference)
#include <cuda_runtime.h>
#include <cuda_fp16.h>
#include <cstdint>

// y = gather_perm(x @ Wv) @ Wo^T   (softmax rowsum == 1 collapse, validated R1)
// tcgen05 unavailable (harness targets sm_103, no 'a') => mma.sync path.
// Legacy HMMA wall: ~17.3 cyc/HMMA/SMSP (worst-SM normalized, R7-R9 invariant).
// R10: kill wave quantization. 64x64 tiles -> 1024 CTAs/GEMM (6.92/SM, 1%
//      imbalance vs 15.6% at 256 CTAs). 2 CTAs/SM preserved via 92KB smem
//      (5-stage ring); 8 warps/SM = the config that achieves the 17.3 rate.

#define MTOT 4096
#define DD   1024
#define BK   64
#define KSB  144                 // smem row stride bytes: conflict-free ldmatrix
#define TILE 64
#define STG_MAT  (TILE * KSB)    // 9216 B per matrix tile
#define OFF_B    STG_MAT
#define STG_BYTES (2 * STG_MAT)  // 18432 B / stage
#define NSTAGE   5
#define SMEM_SZ  (NSTAGE * STG_BYTES)  // 92160 B -> exactly 2 CTAs/SM
#define NCHUNK   (DD / BK)       // 16

__device__ __half g_xh[MTOT * DD];
__device__ __half g_wvt[DD * DD];
__device__ __half g_wo[DD * DD];
__device__ __half g_vh[MTOT * DD];

// ------------------------------------------------------------------ asm utils
static __device__ __forceinline__ uint32_t smem_u32(const void* p) {
    uint32_t a;
    asm("{ .reg .u64 t; cvta.to.shared.u64 t, %1; cvt.u32.u64 %0, t; }" : "=r"(a) : "l"(p));
    return a;
}
#define CP16(s, g) \
    asm volatile("cp.async.cg.shared.global [%0], [%1], 16;" :: "r"(s), "l"(g))
#define CP_COMMIT() asm volatile("cp.async.commit_group;")
#define CP_WAIT3()  asm volatile("cp.async.wait_group 3;")

#define LDSM4(r, addr) \
    asm volatile("ldmatrix.sync.aligned.m8n8.x4.shared.b16 {%0,%1,%2,%3}, [%4];" \
                 : "=r"((r)[0]), "=r"((r)[1]), "=r"((r)[2]), "=r"((r)[3]) : "r"(addr))

#define MMA(d, a, b0, b1) \
    asm volatile("mma.sync.aligned.m16n8k16.row.col.f32.f16.f16.f32 " \
                 "{%0,%1,%2,%3}, {%4,%5,%6,%7}, {%8,%9}, {%0,%1,%2,%3};" \
                 : "+f"((d)[0]), "+f"((d)[1]), "+f"((d)[2]), "+f"((d)[3]) \
                 : "r"((a)[0]), "r"((a)[1]), "r"((a)[2]), "r"((a)[3]), "r"(b0), "r"(b1))

// ------------------------------------------------------------------ GEMM
// MODE 0: V = x @ WvT^T  (A = g_xh [m][k], B = g_wvt [n][k]) -> g_vh (fp16)
// MODE 1: out = gather(V) @ Wo^T (A gathered from g_vh, B = g_wo) -> fp32
template<int MODE>
__global__ void __launch_bounds__(128, 2)
gemm_hmma(float* __restrict__ outp) {
    extern __shared__ char smem[];
    const uint32_t sb = smem_u32(smem);

    const int tid  = threadIdx.x;
    const int lane = tid & 31, wid = tid >> 5;
    const int bm = blockIdx.y * TILE;
    const int bn = blockIdx.x * TILE;

    const __half* A_ = (MODE == 0) ? g_xh  : g_vh;
    const __half* B_ = (MODE == 0) ? g_wvt : g_wo;

    // gather constants (MODE 1): 64-row tile lies in one 128-row head block
    // (bm%128 in {0,64}) -> b, h constant; V-row = boff + ((bm&127)+row)*16 + c
    const int boff = (bm >> 11) << 11;          // b * 2048
    const int hoff = ((bm & 2047) >> 7) * 64;   // h * 64
    const int rbase = bm & 127;                 // 0 or 64

    // ---- global -> smem stage loader: 128 threads, 8 CP16 per chunk
    const int seg  = tid & 7;        // 16B segment of 128B row
    const int row0 = tid >> 3;       // 0..15

    auto issue = [&](int c) {
        const uint32_t sbase = sb + (uint32_t)(c % NSTAGE) * STG_BYTES;
#pragma unroll
        for (int i = 0; i < 4; i++) {
            const int row = row0 + 16 * i;
            size_t aoff;
            if (MODE == 0) {
                aoff = (size_t)(bm + row) * DD + c * BK + seg * 8;
            } else {
                aoff = (size_t)(boff + (rbase + row) * 16 + c) * DD + hoff + seg * 8;
            }
            const size_t bo = (size_t)(bn + row) * DD + c * BK + seg * 8;
            CP16(sbase + row * KSB + seg * 16,         A_ + aoff);
            CP16(sbase + OFF_B + row * KSB + seg * 16, B_ + bo);
        }
        CP_COMMIT();
    };

    // ---- warp tiling: 2(m) x 2(n) warps of 32x32
    const int warp_m = (wid >> 1) * 32;
    const int warp_n = (wid & 1) * 32;
    const int lr = lane & 15;            // ldmatrix row within 16
    const int lcb = (lane >> 4) * 16;    // ldmatrix k-half byte offset

    float acc[2][4][4];
#pragma unroll
    for (int mt = 0; mt < 2; mt++)
#pragma unroll
        for (int j = 0; j < 4; j++)
#pragma unroll
            for (int q = 0; q < 4; q++) acc[mt][j][q] = 0.f;

    issue(0); issue(1); issue(2); issue(3);

    for (int c = 0; c < NCHUNK; c++) {
        CP_WAIT3();          // in-order groups: group c complete
        __syncthreads();
        // stage (c+4)%5 == (c-1)%5 was last read in compute(c-1); all warps
        // passed the barrier above -> overwrite safe.
        if (c + 4 < NCHUNK) issue(c + 4);

        const uint32_t sbase = sb + (uint32_t)(c % NSTAGE) * STG_BYTES;
#pragma unroll
        for (int kk = 0; kk < 4; kk++) {
            const uint32_t kb = kk * 32 + lcb;  // k byte offset within 128B row

            uint32_t aa[2][4], bb[2][4];
#pragma unroll
            for (int mt = 0; mt < 2; mt++)
                LDSM4(aa[mt], sbase + (warp_m + mt * 16 + lr) * KSB + kb);
#pragma unroll
            for (int nt = 0; nt < 2; nt++)
                LDSM4(bb[nt], sbase + OFF_B + (warp_n + nt * 16 + lr) * KSB + kb);

#pragma unroll
            for (int mt = 0; mt < 2; mt++)
#pragma unroll
                for (int nt = 0; nt < 2; nt++) {
                    MMA(acc[mt][2 * nt],     aa[mt], bb[nt][0], bb[nt][2]);
                    MMA(acc[mt][2 * nt + 1], aa[mt], bb[nt][1], bb[nt][3]);
                }
        }
    }

    // ---- epilogue (fragment layout: d0,d1 -> row lane>>2, d2,d3 -> +8)
#pragma unroll
    for (int mt = 0; mt < 2; mt++) {
        const int m0 = bm + warp_m + mt * 16 + (lane >> 2);
#pragma unroll
        for (int j = 0; j < 4; j++) {
            const int n0 = bn + warp_n + j * 8 + (lane & 3) * 2;
            const float* d = acc[mt][j];
            if (MODE == 0) {
#pragma unroll
                for (int half_ = 0; half_ < 2; half_++) {
                    const size_t o = (size_t)(m0 + 8 * half_) * DD + n0;
                    *(__half2*)&g_vh[o] =
                        __floats2half2_rn(d[2 * half_], d[2 * half_ + 1]);
                }
            } else {
#pragma unroll
                for (int half_ = 0; half_ < 2; half_++) {
                    const size_t o = (size_t)(m0 + 8 * half_) * DD + n0;
                    *(float2*)&outp[o] = make_float2(d[2 * half_], d[2 * half_ + 1]);
                }
            }
        }
    }
}

// ------------------------------------------------------------------ fused prep
// blocks [0,2048): x fp32->fp16, 2 float4 per thread
// blocks [2048,3072): Wo convert + WvT transpose tile
__global__ void k_prep(const float* __restrict__ x,
                       const float* __restrict__ Wv,
                       const float* __restrict__ Wo) {
    const int blk = blockIdx.x;
    if (blk < 2048) {
        const int base = blk * 512 + threadIdx.x;
#pragma unroll
        for (int u = 0; u < 2; u++) {
            const int i = base + u * 256;
            float4 v = ((const float4*)x)[i];
            ((__half2*)g_xh)[2 * i]     = __floats2half2_rn(v.x, v.y);
            ((__half2*)g_xh)[2 * i + 1] = __floats2half2_rn(v.z, v.w);
        }
    } else {
        const int t = blk - 2048;   // 0..1023
        const int i = t * 256 + threadIdx.x;
        float4 v = ((const float4*)Wo)[i];
        ((__half2*)g_wo)[2 * i]     = __floats2half2_rn(v.x, v.y);
        ((__half2*)g_wo)[2 * i + 1] = __floats2half2_rn(v.z, v.w);
        // WvT[n][k] = Wv[k][n] for one 32x32 tile
        __shared__ float tt[32][33];
        const int bx = (t & 31) * 32, by = (t >> 5) * 32;
        const int tx = threadIdx.x & 31, ty = threadIdx.x >> 5;  // 32 x 8
#pragma unroll
        for (int j = 0; j < 32; j += 8)
            tt[ty + j][tx] = Wv[(size_t)(by + ty + j) * DD + bx + tx];
        __syncthreads();
#pragma unroll
        for (int j = 0; j < 32; j += 8)
            g_wvt[(size_t)(bx + ty + j) * DD + by + tx] =
                __float2half_rn(tt[tx][ty + j]);
    }
}

// ------------------------------------------------------------------ launch
// inputs: x, mask, Wq, Wk, Wv, Wo -> fp32 out [B,T,D]
extern "C" void kernel_launch(void* const* d_in, const int* in_sizes, int n_in,
                              void* d_out, int out_size) {
    const float* x  = (const float*)d_in[0];
    const float* Wv = (const float*)d_in[4];
    const float* Wo = (const float*)d_in[5];
    float* out = (float*)d_out;

    cudaFuncSetAttribute(gemm_hmma<0>, cudaFuncAttributeMaxDynamicSharedMemorySize, SMEM_SZ);
    cudaFuncSetAttribute(gemm_hmma<1>, cudaFuncAttributeMaxDynamicSharedMemorySize, SMEM_SZ);

    k_prep<<<3072, 256>>>(x, Wv, Wo);

    dim3 grid(DD / TILE, MTOT / TILE);   // (16, 64) = 1024 CTAs
    gemm_hmma<0><<<grid, 128, SMEM_SZ>>>(nullptr);
    gemm_hmma<1><<<grid, 128, SMEM_SZ>>>(out);
}

// round 12
// speedup vs baseline: 1.1842x; 1.1842x over previous
#include <cuda_runtime.h>
#include <cuda_fp16.h>
#include <cstdint>

// y = gather_perm(x @ Wv) @ Wo^T   (softmax rowsum == 1 collapse, validated R1)
// tcgen05 unavailable (harness targets sm_103, no 'a') => mma.sync path.
// Legacy HMMA wall ~255-260 TF/s (R3-R10 invariant); 128x128/64x64/8-warp
// config is the efficiency point (R10's 64x64 tiles regressed).
// R12: R11 prep had a 4x block-count overrun on the x section (2048 blocks
//      covering 2048 float4 each vs 1M float4 total) -> OOB reads. Fixed:
//      512 x-blocks. GEMMs = exact R9 (78.7us best).

#define MTOT 4096
#define DD   1024
#define BK   64
#define KSB  144                 // smem row stride bytes: conflict-free ldmatrix
#define STG_MAT  (128 * KSB)     // 18432 B per matrix tile
#define OFF_B    STG_MAT
#define STG_BYTES (2 * STG_MAT)  // 36864 B / stage
#define NSTAGE   3
#define SMEM_SZ  (NSTAGE * STG_BYTES)  // 110592 B ; 2 CTAs/SM
#define NCHUNK   (DD / BK)       // 16

__device__ __half g_xh[MTOT * DD];
__device__ __half g_wvt[DD * DD];
__device__ __half g_wo[DD * DD];
__device__ __half g_vh[MTOT * DD];

// ------------------------------------------------------------------ asm utils
static __device__ __forceinline__ uint32_t smem_u32(const void* p) {
    uint32_t a;
    asm("{ .reg .u64 t; cvta.to.shared.u64 t, %1; cvt.u32.u64 %0, t; }" : "=r"(a) : "l"(p));
    return a;
}
#define CP16(s, g) \
    asm volatile("cp.async.cg.shared.global [%0], [%1], 16;" :: "r"(s), "l"(g))
#define CP_COMMIT() asm volatile("cp.async.commit_group;")
#define CP_WAIT1()  asm volatile("cp.async.wait_group 1;")

#define LDSM4(r, addr) \
    asm volatile("ldmatrix.sync.aligned.m8n8.x4.shared.b16 {%0,%1,%2,%3}, [%4];" \
                 : "=r"((r)[0]), "=r"((r)[1]), "=r"((r)[2]), "=r"((r)[3]) : "r"(addr))

#define MMA(d, a, b0, b1) \
    asm volatile("mma.sync.aligned.m16n8k16.row.col.f32.f16.f16.f32 " \
                 "{%0,%1,%2,%3}, {%4,%5,%6,%7}, {%8,%9}, {%0,%1,%2,%3};" \
                 : "+f"((d)[0]), "+f"((d)[1]), "+f"((d)[2]), "+f"((d)[3]) \
                 : "r"((a)[0]), "r"((a)[1]), "r"((a)[2]), "r"((a)[3]), "r"(b0), "r"(b1))

// ------------------------------------------------------------------ GEMM (R9)
// MODE 0: V = x @ WvT^T  (A = g_xh [m][k], B = g_wvt [n][k]) -> g_vh (fp16)
// MODE 1: out = gather(V) @ Wo^T (A gathered from g_vh, B = g_wo) -> fp32
template<int MODE>
__global__ void __launch_bounds__(128, 2)
gemm_hmma(float* __restrict__ outp) {
    extern __shared__ char smem[];
    const uint32_t sb = smem_u32(smem);

    const int tid  = threadIdx.x;
    const int lane = tid & 31, wid = tid >> 5;
    const int bm = blockIdx.y * 128;
    const int bn = blockIdx.x * 128;

    const __half* A_ = (MODE == 0) ? g_xh  : g_vh;
    const __half* B_ = (MODE == 0) ? g_wvt : g_wo;

    // gather constants (MODE 1): with BK=64 chunks, k>>6 == c exactly.
    const int boff = (bm >> 11) << 11;          // b * 2048
    const int hoff = ((bm & 2047) >> 7) * 64;   // h * 64

    // ---- global -> smem stage loader: 128 threads, 16 CP16 per thread
    const int seg  = tid & 7;        // 16B segment of 128B row
    const int row0 = tid >> 3;       // 0..15

    auto issue = [&](int c) {
        const uint32_t sbase = sb + (uint32_t)(c % NSTAGE) * STG_BYTES;
#pragma unroll
        for (int i = 0; i < 8; i++) {
            const int row = row0 + 16 * i;
            size_t aoff;
            if (MODE == 0) {
                aoff = (size_t)(bm + row) * DD + c * BK + seg * 8;
            } else {
                aoff = (size_t)(boff + row * 16 + c) * DD + hoff + seg * 8;
            }
            const size_t bo = (size_t)(bn + row) * DD + c * BK + seg * 8;
            CP16(sbase + row * KSB + seg * 16,         A_ + aoff);
            CP16(sbase + OFF_B + row * KSB + seg * 16, B_ + bo);
        }
        CP_COMMIT();
    };

    // ---- warp tiling: 2(m) x 2(n) warps of 64x64
    const int warp_m = (wid >> 1) * 64;
    const int warp_n = (wid & 1) * 64;
    const int lr = lane & 15;            // ldmatrix row within 16
    const int lcb = (lane >> 4) * 16;    // ldmatrix k-half byte offset

    float acc[4][8][4];
#pragma unroll
    for (int mt = 0; mt < 4; mt++)
#pragma unroll
        for (int j = 0; j < 8; j++)
#pragma unroll
            for (int q = 0; q < 4; q++) acc[mt][j][q] = 0.f;

    issue(0);
    issue(1);

    for (int c = 0; c < NCHUNK; c++) {
        CP_WAIT1();          // in-order groups: group c complete
        __syncthreads();
        // stage (c+2)%3 == (c-1)%3 was last read in compute(c-1); all warps
        // passed the barrier above -> overwrite safe.
        if (c + 2 < NCHUNK) issue(c + 2);

        const uint32_t sbase = sb + (uint32_t)(c % NSTAGE) * STG_BYTES;
#pragma unroll
        for (int kk = 0; kk < 4; kk++) {
            const uint32_t kb = kk * 32 + lcb;  // k byte offset within 128B row

            uint32_t aa[4][4], bb[4][4];
#pragma unroll
            for (int mt = 0; mt < 4; mt++)
                LDSM4(aa[mt], sbase + (warp_m + mt * 16 + lr) * KSB + kb);
#pragma unroll
            for (int nt = 0; nt < 4; nt++)
                LDSM4(bb[nt], sbase + OFF_B + (warp_n + nt * 16 + lr) * KSB + kb);

#pragma unroll
            for (int mt = 0; mt < 4; mt++)
#pragma unroll
                for (int nt = 0; nt < 4; nt++) {
                    MMA(acc[mt][2 * nt],     aa[mt], bb[nt][0], bb[nt][2]);
                    MMA(acc[mt][2 * nt + 1], aa[mt], bb[nt][1], bb[nt][3]);
                }
        }
    }

    // ---- epilogue (fragment layout: d0,d1 -> row lane>>2, d2,d3 -> +8)
#pragma unroll
    for (int mt = 0; mt < 4; mt++) {
        const int m0 = bm + warp_m + mt * 16 + (lane >> 2);
#pragma unroll
        for (int j = 0; j < 8; j++) {
            const int n0 = bn + warp_n + j * 8 + (lane & 3) * 2;
            const float* d = acc[mt][j];
            if (MODE == 0) {
#pragma unroll
                for (int half_ = 0; half_ < 2; half_++) {
                    const size_t o = (size_t)(m0 + 8 * half_) * DD + n0;
                    *(__half2*)&g_vh[o] =
                        __floats2half2_rn(d[2 * half_], d[2 * half_ + 1]);
                }
            } else {
#pragma unroll
                for (int half_ = 0; half_ < 2; half_++) {
                    const size_t o = (size_t)(m0 + 8 * half_) * DD + n0;
                    *(float2*)&outp[o] = make_float2(d[2 * half_], d[2 * half_ + 1]);
                }
            }
        }
    }
}

// ------------------------------------------------------------------ fused prep
// x has MTOT*DD/4 = 1,048,576 float4; 2048 float4 per block -> 512 blocks.
// blocks [0,512):    x fp32->fp16, 8 float4/thread in two MLP-4 batches
// blocks [512,768):  Wo convert, 4 float4/thread (256*1024 = 262,144 = DD*DD/4)
// blocks [768,1792): WvT transpose tile (32x32)
__global__ void k_prep(const float* __restrict__ x,
                       const float* __restrict__ Wv,
                       const float* __restrict__ Wo) {
    const int blk = blockIdx.x;
    if (blk < 512) {
        const int base = blk * 2048 + threadIdx.x;
#pragma unroll
        for (int g = 0; g < 2; g++) {
            float4 v[4];
#pragma unroll
            for (int u = 0; u < 4; u++)                 // 4 independent LDG (MLP 4)
                v[u] = ((const float4*)x)[base + (g * 4 + u) * 256];
#pragma unroll
            for (int u = 0; u < 4; u++) {
                const int i = base + (g * 4 + u) * 256;
                ((__half2*)g_xh)[2 * i]     = __floats2half2_rn(v[u].x, v[u].y);
                ((__half2*)g_xh)[2 * i + 1] = __floats2half2_rn(v[u].z, v[u].w);
            }
        }
    } else if (blk < 768) {
        const int base = (blk - 512) * 1024 + threadIdx.x;
        float4 v[4];
#pragma unroll
        for (int u = 0; u < 4; u++)
            v[u] = ((const float4*)Wo)[base + u * 256];
#pragma unroll
        for (int u = 0; u < 4; u++) {
            const int i = base + u * 256;
            ((__half2*)g_wo)[2 * i]     = __floats2half2_rn(v[u].x, v[u].y);
            ((__half2*)g_wo)[2 * i + 1] = __floats2half2_rn(v[u].z, v[u].w);
        }
    } else {
        // WvT[n][k] = Wv[k][n], 1024 tiles of 32x32
        const int t = blk - 768;
        __shared__ float tt[32][33];
        const int bx = (t & 31) * 32, by = (t >> 5) * 32;
        const int tx = threadIdx.x & 31, ty = threadIdx.x >> 5;  // 32 x 8
#pragma unroll
        for (int j = 0; j < 32; j += 8)
            tt[ty + j][tx] = Wv[(size_t)(by + ty + j) * DD + bx + tx];
        __syncthreads();
#pragma unroll
        for (int j = 0; j < 32; j += 8)
            g_wvt[(size_t)(bx + ty + j) * DD + by + tx] =
                __float2half_rn(tt[tx][ty + j]);
    }
}

// ------------------------------------------------------------------ launch
// inputs: x, mask, Wq, Wk, Wv, Wo -> fp32 out [B,T,D]
extern "C" void kernel_launch(void* const* d_in, const int* in_sizes, int n_in,
                              void* d_out, int out_size) {
    const float* x  = (const float*)d_in[0];
    const float* Wv = (const float*)d_in[4];
    const float* Wo = (const float*)d_in[5];
    float* out = (float*)d_out;

    cudaFuncSetAttribute(gemm_hmma<0>, cudaFuncAttributeMaxDynamicSharedMemorySize, SMEM_SZ);
    cudaFuncSetAttribute(gemm_hmma<1>, cudaFuncAttributeMaxDynamicSharedMemorySize, SMEM_SZ);

    k_prep<<<1792, 256>>>(x, Wv, Wo);

    dim3 grid(DD / 128, MTOT / 128);   // (8, 32) = 256 CTAs
    gemm_hmma<0><<<grid, 128, SMEM_SZ>>>(nullptr);
    gemm_hmma<1><<<grid, 128, SMEM_SZ>>>(out);
}

// round 13
// speedup vs baseline: 1.1847x; 1.0004x over previous
#include <cuda_runtime.h>
#include <cuda_fp16.h>
#include <cstdint>

// y = gather_perm(x @ Wv) @ Wo^T   (softmax rowsum == 1 collapse, validated R1)
// tcgen05 unavailable (harness targets sm_103, no 'a') => mma.sync path.
// Legacy HMMA wall ~255-260 TF/s; 128x128 CTA / 64x64 warp / 8 warps/SM is the
// efficiency point (R10 regression proved smaller tiles lose more than the
// 15.6% wave imbalance they recover). GEMMs frozen at R9/R12 form.
// R13: prep rewrite only — STG.128 packed stores, 64x64 transpose tiles,
//      576 fat blocks (was 1792 thin).

#define MTOT 4096
#define DD   1024
#define BK   64
#define KSB  144                 // smem row stride bytes: conflict-free ldmatrix
#define STG_MAT  (128 * KSB)     // 18432 B per matrix tile
#define OFF_B    STG_MAT
#define STG_BYTES (2 * STG_MAT)  // 36864 B / stage
#define NSTAGE   3
#define SMEM_SZ  (NSTAGE * STG_BYTES)  // 110592 B ; 2 CTAs/SM
#define NCHUNK   (DD / BK)       // 16

__device__ __half g_xh[MTOT * DD];
__device__ __half g_wvt[DD * DD];
__device__ __half g_wo[DD * DD];
__device__ __half g_vh[MTOT * DD];

// ------------------------------------------------------------------ asm utils
static __device__ __forceinline__ uint32_t smem_u32(const void* p) {
    uint32_t a;
    asm("{ .reg .u64 t; cvta.to.shared.u64 t, %1; cvt.u32.u64 %0, t; }" : "=r"(a) : "l"(p));
    return a;
}
#define CP16(s, g) \
    asm volatile("cp.async.cg.shared.global [%0], [%1], 16;" :: "r"(s), "l"(g))
#define CP_COMMIT() asm volatile("cp.async.commit_group;")
#define CP_WAIT1()  asm volatile("cp.async.wait_group 1;")

#define LDSM4(r, addr) \
    asm volatile("ldmatrix.sync.aligned.m8n8.x4.shared.b16 {%0,%1,%2,%3}, [%4];" \
                 : "=r"((r)[0]), "=r"((r)[1]), "=r"((r)[2]), "=r"((r)[3]) : "r"(addr))

#define MMA(d, a, b0, b1) \
    asm volatile("mma.sync.aligned.m16n8k16.row.col.f32.f16.f16.f32 " \
                 "{%0,%1,%2,%3}, {%4,%5,%6,%7}, {%8,%9}, {%0,%1,%2,%3};" \
                 : "+f"((d)[0]), "+f"((d)[1]), "+f"((d)[2]), "+f"((d)[3]) \
                 : "r"((a)[0]), "r"((a)[1]), "r"((a)[2]), "r"((a)[3]), "r"(b0), "r"(b1))

// ------------------------------------------------------------------ GEMM (R9)
// MODE 0: V = x @ WvT^T  (A = g_xh [m][k], B = g_wvt [n][k]) -> g_vh (fp16)
// MODE 1: out = gather(V) @ Wo^T (A gathered from g_vh, B = g_wo) -> fp32
template<int MODE>
__global__ void __launch_bounds__(128, 2)
gemm_hmma(float* __restrict__ outp) {
    extern __shared__ char smem[];
    const uint32_t sb = smem_u32(smem);

    const int tid  = threadIdx.x;
    const int lane = tid & 31, wid = tid >> 5;
    const int bm = blockIdx.y * 128;
    const int bn = blockIdx.x * 128;

    const __half* A_ = (MODE == 0) ? g_xh  : g_vh;
    const __half* B_ = (MODE == 0) ? g_wvt : g_wo;

    // gather constants (MODE 1): with BK=64 chunks, k>>6 == c exactly.
    const int boff = (bm >> 11) << 11;          // b * 2048
    const int hoff = ((bm & 2047) >> 7) * 64;   // h * 64

    // ---- global -> smem stage loader: 128 threads, 16 CP16 per thread
    const int seg  = tid & 7;        // 16B segment of 128B row
    const int row0 = tid >> 3;       // 0..15

    auto issue = [&](int c) {
        const uint32_t sbase = sb + (uint32_t)(c % NSTAGE) * STG_BYTES;
#pragma unroll
        for (int i = 0; i < 8; i++) {
            const int row = row0 + 16 * i;
            size_t aoff;
            if (MODE == 0) {
                aoff = (size_t)(bm + row) * DD + c * BK + seg * 8;
            } else {
                aoff = (size_t)(boff + row * 16 + c) * DD + hoff + seg * 8;
            }
            const size_t bo = (size_t)(bn + row) * DD + c * BK + seg * 8;
            CP16(sbase + row * KSB + seg * 16,         A_ + aoff);
            CP16(sbase + OFF_B + row * KSB + seg * 16, B_ + bo);
        }
        CP_COMMIT();
    };

    // ---- warp tiling: 2(m) x 2(n) warps of 64x64
    const int warp_m = (wid >> 1) * 64;
    const int warp_n = (wid & 1) * 64;
    const int lr = lane & 15;            // ldmatrix row within 16
    const int lcb = (lane >> 4) * 16;    // ldmatrix k-half byte offset

    float acc[4][8][4];
#pragma unroll
    for (int mt = 0; mt < 4; mt++)
#pragma unroll
        for (int j = 0; j < 8; j++)
#pragma unroll
            for (int q = 0; q < 4; q++) acc[mt][j][q] = 0.f;

    issue(0);
    issue(1);

    for (int c = 0; c < NCHUNK; c++) {
        CP_WAIT1();          // in-order groups: group c complete
        __syncthreads();
        // stage (c+2)%3 == (c-1)%3 was last read in compute(c-1); all warps
        // passed the barrier above -> overwrite safe.
        if (c + 2 < NCHUNK) issue(c + 2);

        const uint32_t sbase = sb + (uint32_t)(c % NSTAGE) * STG_BYTES;
#pragma unroll
        for (int kk = 0; kk < 4; kk++) {
            const uint32_t kb = kk * 32 + lcb;  // k byte offset within 128B row

            uint32_t aa[4][4], bb[4][4];
#pragma unroll
            for (int mt = 0; mt < 4; mt++)
                LDSM4(aa[mt], sbase + (warp_m + mt * 16 + lr) * KSB + kb);
#pragma unroll
            for (int nt = 0; nt < 4; nt++)
                LDSM4(bb[nt], sbase + OFF_B + (warp_n + nt * 16 + lr) * KSB + kb);

#pragma unroll
            for (int mt = 0; mt < 4; mt++)
#pragma unroll
                for (int nt = 0; nt < 4; nt++) {
                    MMA(acc[mt][2 * nt],     aa[mt], bb[nt][0], bb[nt][2]);
                    MMA(acc[mt][2 * nt + 1], aa[mt], bb[nt][1], bb[nt][3]);
                }
        }
    }

    // ---- epilogue (fragment layout: d0,d1 -> row lane>>2, d2,d3 -> +8)
#pragma unroll
    for (int mt = 0; mt < 4; mt++) {
        const int m0 = bm + warp_m + mt * 16 + (lane >> 2);
#pragma unroll
        for (int j = 0; j < 8; j++) {
            const int n0 = bn + warp_n + j * 8 + (lane & 3) * 2;
            const float* d = acc[mt][j];
            if (MODE == 0) {
#pragma unroll
                for (int half_ = 0; half_ < 2; half_++) {
                    const size_t o = (size_t)(m0 + 8 * half_) * DD + n0;
                    *(__half2*)&g_vh[o] =
                        __floats2half2_rn(d[2 * half_], d[2 * half_ + 1]);
                }
            } else {
#pragma unroll
                for (int half_ = 0; half_ < 2; half_++) {
                    const size_t o = (size_t)(m0 + 8 * half_) * DD + n0;
                    *(float2*)&outp[o] = make_float2(d[2 * half_], d[2 * half_ + 1]);
                }
            }
        }
    }
}

// ------------------------------------------------------------------ prep
static __device__ __forceinline__ uint32_t h2u(__half2 h) {
    return *reinterpret_cast<uint32_t*>(&h);
}
// pack 2 float4 -> 8 halves -> uint4
static __device__ __forceinline__ uint4 pack8(float4 a, float4 b) {
    uint4 o;
    o.x = h2u(__floats2half2_rn(a.x, a.y));
    o.y = h2u(__floats2half2_rn(a.z, a.w));
    o.z = h2u(__floats2half2_rn(b.x, b.y));
    o.w = h2u(__floats2half2_rn(b.z, b.w));
    return o;
}

// blocks [0,256):   x fp32->fp16   (256 blk * 256 thr * 8 uint4 = 524288 = MTOT*DD/8)
// blocks [256,320): Wo fp32->fp16  (64 blk  * 256 thr * 8 uint4 = 131072 = DD*DD/8)
// blocks [320,576): WvT transpose+convert, 64x64 tiles (16x16 grid)
__global__ void k_prep(const float* __restrict__ x,
                       const float* __restrict__ Wv,
                       const float* __restrict__ Wo) {
    const int blk = blockIdx.x, tid = threadIdx.x;
    if (blk < 320) {
        const bool is_x = (blk < 256);
        const float4* src = (const float4*)(is_x ? x : Wo);
        uint4* dst = (uint4*)(is_x ? g_xh : g_wo);
        const int jb = (is_x ? blk : blk - 256) * 2048 + tid;   // uint4 index
#pragma unroll
        for (int g = 0; g < 4; g++) {
            const int j0 = jb + (2 * g) * 256;
            const int j1 = jb + (2 * g + 1) * 256;
            float4 v0 = src[2 * j0], v1 = src[2 * j0 + 1];      // 4 LDG in flight
            float4 v2 = src[2 * j1], v3 = src[2 * j1 + 1];
            dst[j0] = pack8(v0, v1);
            dst[j1] = pack8(v2, v3);
        }
    } else {
        // WvT[n][k] = Wv[k][n]; 64x64 tile t: k-base = (t&15)*64, n-base = (t>>4)*64
        const int t  = blk - 320;
        const int tk = (t & 15) * 64, tn = (t >> 4) * 64;
        __shared__ float tt[64][65];
#pragma unroll
        for (int i = 0; i < 16; i++) {
            const int idx = tid + 256 * i;
            const int r = idx >> 6, cc = idx & 63;
            tt[r][cc] = Wv[(size_t)(tk + r) * DD + tn + cc];
        }
        __syncthreads();
        // writer: 4 threads per n-row cover 64 k (2 x uint4 each, coalesced 128B/row)
        const int nl   = tid >> 2;           // 0..63 local n
        const int kseg = (tid & 3) * 16;     // k segment base
        uint32_t w[8];
#pragma unroll
        for (int p = 0; p < 8; p++)
            w[p] = h2u(__floats2half2_rn(tt[kseg + 2 * p][nl], tt[kseg + 2 * p + 1][nl]));
        uint4* dst = (uint4*)&g_wvt[(size_t)(tn + nl) * DD + tk + kseg];
        dst[0] = make_uint4(w[0], w[1], w[2], w[3]);
        dst[1] = make_uint4(w[4], w[5], w[6], w[7]);
    }
}

// ------------------------------------------------------------------ launch
// inputs: x, mask, Wq, Wk, Wv, Wo -> fp32 out [B,T,D]
extern "C" void kernel_launch(void* const* d_in, const int* in_sizes, int n_in,
                              void* d_out, int out_size) {
    const float* x  = (const float*)d_in[0];
    const float* Wv = (const float*)d_in[4];
    const float* Wo = (const float*)d_in[5];
    float* out = (float*)d_out;

    cudaFuncSetAttribute(gemm_hmma<0>, cudaFuncAttributeMaxDynamicSharedMemorySize, SMEM_SZ);
    cudaFuncSetAttribute(gemm_hmma<1>, cudaFuncAttributeMaxDynamicSharedMemorySize, SMEM_SZ);

    k_prep<<<576, 256>>>(x, Wv, Wo);

    dim3 grid(DD / 128, MTOT / 128);   // (8, 32) = 256 CTAs
    gemm_hmma<0><<<grid, 128, SMEM_SZ>>>(nullptr);
    gemm_hmma<1><<<grid, 128, SMEM_SZ>>>(out);
}